// round 10
// baseline (speedup 1.0000x reference)
#include <cuda_runtime.h>
#include <cuda_fp16.h>
#include <cstdint>

#define Bb 4
#define Qq 512
#define Kk 1024
#define VDd 256
#define Hh 128

#define AT2 68          // av attn smem stride
#define NSLAB 4
#define SLABK 256

// Scratch (no allocations allowed). g_qp/g_kp hold TANH of projections.
__device__ __align__(16) float g_qp[Bb * Qq * Hh];             // 1 MB
__device__ __align__(16) float g_kp[Bb * Kk * Hh];             // 2 MB
__device__ __align__(16) float g_sc[Bb * Qq * Kk];             // 8 MB
__device__ __align__(16) float g_pt[NSLAB][Bb * Qq * VDd];     // 8 MB partials

__device__ __forceinline__ float tanh_fast(float x) {
    float y;
    asm("tanh.approx.f32 %0, %1;" : "=f"(y) : "f"(x));
    return y;
}
__device__ __forceinline__ float rcp_fast(float x) {
    float y;
    asm("rcp.approx.f32 %0, %1;" : "=f"(y) : "f"(x));
    return y;
}

// ---------------------------------------------------------------------------
// Combined projection + tanh: g_qp = tanh(queries@W_q), g_kp = tanh(keys@W_k).
// tanh clamped to +-(1-6e-8) so the scores denominator 1+tq*tk stays > 0.
// ---------------------------------------------------------------------------
__global__ void __launch_bounds__(256)
proj_kernel(const float* __restrict__ queries,
            const float* __restrict__ W_q,
            const float* __restrict__ keys,
            const float* __restrict__ W_k) {
    __shared__ __align__(16) float a_s[16][260];
    __shared__ __align__(16) float w_t[128][36];

    const int bx = blockIdx.x;
    const float* A; const float* W; float* C; int row0;
    if (bx < (Bb * Qq) / 16) { A = queries; W = W_q; C = g_qp; row0 = bx * 16; }
    else { A = keys; W = W_k; C = g_kp; row0 = (bx - (Bb * Qq) / 16) * 16; }

    const int tid = threadIdx.x;

    const float4* A4 = (const float4*)(A + (size_t)row0 * 256);
    #pragma unroll
    for (int i = 0; i < 4; i++) {
        int e = i * 256 + tid;
        ((float4*)&a_s[e >> 6][0])[e & 63] = A4[e];
    }

    const int col = tid & 127;
    const int rg  = tid >> 7;
    float acc[8];
    #pragma unroll
    for (int i = 0; i < 8; i++) acc[i] = 0.f;

    for (int dc = 0; dc < 256; dc += 32) {
        __syncthreads();
        #pragma unroll
        for (int i = 0; i < 16; i++) {
            int idx = i * 256 + tid;
            int r = idx >> 7, c = idx & 127;
            w_t[c][r] = W[(size_t)(dc + r) * 128 + c];
        }
        __syncthreads();
        const float4* wv4 = (const float4*)&w_t[col][0];
        #pragma unroll
        for (int d4 = 0; d4 < 8; d4++) {
            float4 wv = wv4[d4];
            #pragma unroll
            for (int i = 0; i < 8; i++) {
                float4 av = ((const float4*)&a_s[rg * 8 + i][dc])[d4];
                acc[i] += av.x * wv.x + av.y * wv.y + av.z * wv.z + av.w * wv.w;
            }
        }
    }
    __syncthreads();
    #pragma unroll
    for (int i = 0; i < 8; i++) {
        float t = tanh_fast(acc[i]);
        t = fminf(fmaxf(t, -0.99999994f), 0.99999994f);
        C[(size_t)(row0 + rg * 8 + i) * 128 + col] = t;
    }
}

// ---------------------------------------------------------------------------
// Scores via tanh addition formula (NO tanh in hot loop):
//   w*tanh(q+k) = (w*tk + w*tq) / (1 + tq*tk)
// Tiles transposed [h][row] in dynamic smem: tq (32KB), w*tq (32KB), tk (32KB).
// Inner per element: FFMA(num) + FFMA(den) + FMNMX + MUFU.RCP + FFMA(acc).
// 64q x 64k tile, 4x4 micro-tile. Masked tiles exit immediately.
// ---------------------------------------------------------------------------
__global__ void __launch_bounds__(256)
scores_kernel(const float* __restrict__ w_v,
              const int* __restrict__ valid_lens) {
    const int b  = blockIdx.z;
    const int k0 = blockIdx.x * 64;
    if (k0 >= valid_lens[b]) return;
    const int q0 = blockIdx.y * 64;

    extern __shared__ float sm[];
    float* qt  = sm;                 // [h][qrow] 128*64
    float* wqt = qt + 128 * 64;      // [h][qrow] w_h * tq
    float* kt  = wqt + 128 * 64;     // [h][krow]
    float* ws  = kt + 128 * 64;      // 128

    const int tid = threadIdx.x;
    if (tid < 128) ws[tid] = w_v[tid];
    __syncthreads();

    const float4* qp4 = (const float4*)(g_qp + (size_t)(b * Qq + q0) * Hh);
    const float4* kp4 = (const float4*)(g_kp + (size_t)(b * Kk + k0) * Hh);

    // Load + transpose. Task t: row = t&63, c4 = t>>6 (f4 h-col 0..31).
    #pragma unroll
    for (int i = 0; i < 8; i++) {
        int t   = i * 256 + tid;
        int row = t & 63, c4 = t >> 6;
        float4 qv = qp4[row * 32 + c4];
        float4 kv = kp4[row * 32 + c4];
        int h = 4 * c4;
        qt[(h + 0) * 64 + row] = qv.x;
        qt[(h + 1) * 64 + row] = qv.y;
        qt[(h + 2) * 64 + row] = qv.z;
        qt[(h + 3) * 64 + row] = qv.w;
        wqt[(h + 0) * 64 + row] = ws[h + 0] * qv.x;
        wqt[(h + 1) * 64 + row] = ws[h + 1] * qv.y;
        wqt[(h + 2) * 64 + row] = ws[h + 2] * qv.z;
        wqt[(h + 3) * 64 + row] = ws[h + 3] * qv.w;
        kt[(h + 0) * 64 + row] = kv.x;
        kt[(h + 1) * 64 + row] = kv.y;
        kt[(h + 2) * 64 + row] = kv.z;
        kt[(h + 3) * 64 + row] = kv.w;
    }
    __syncthreads();

    const int tx = tid & 15;   // k rows 4tx..4tx+3
    const int ty = tid >> 4;   // q rows 4ty..4ty+3

    float acc[4][4];
    #pragma unroll
    for (int i = 0; i < 4; i++)
        #pragma unroll
        for (int j = 0; j < 4; j++) acc[i][j] = 0.f;

    #pragma unroll 4
    for (int h = 0; h < 128; h++) {
        float w = ws[h];
        float4 qv = *(const float4*)&qt[h * 64 + 4 * ty];
        float4 wq = *(const float4*)&wqt[h * 64 + 4 * ty];
        float4 kv = *(const float4*)&kt[h * 64 + 4 * tx];
        float qa[4]  = {qv.x, qv.y, qv.z, qv.w};
        float wqa[4] = {wq.x, wq.y, wq.z, wq.w};
        float ka[4]  = {kv.x, kv.y, kv.z, kv.w};
        #pragma unroll
        for (int i = 0; i < 4; i++) {
            #pragma unroll
            for (int j = 0; j < 4; j++) {
                float num = fmaf(w, ka[j], wqa[i]);
                float den = fmaf(qa[i], ka[j], 1.0f);
                den = fmaxf(den, 1e-30f);
                acc[i][j] = fmaf(num, rcp_fast(den), acc[i][j]);
            }
        }
    }

    #pragma unroll
    for (int i = 0; i < 4; i++) {
        float4 r = make_float4(acc[i][0], acc[i][1], acc[i][2], acc[i][3]);
        *(float4*)&g_sc[(size_t)(b * Qq + q0 + 4 * ty + i) * Kk + k0 + 4 * tx] = r;
    }
}

// ---------------------------------------------------------------------------
// Softmax over k < vl; zeros written up to roundup(vl,64) (AV reads that far).
// ---------------------------------------------------------------------------
__global__ void softmax_kernel(const int* __restrict__ valid_lens) {
    const int row = blockIdx.x;
    const int b   = row >> 9;
    const int vl  = valid_lens[b];
    const int vl64 = (vl + 63) & ~63;
    const int tid = threadIdx.x;
    const float NINF = __int_as_float(0xff800000);

    float4* p = (float4*)&g_sc[(size_t)row * Kk];
    const int k = 4 * tid;
    const bool live = (k < vl64);
    float4 v = live ? p[tid] : make_float4(NINF, NINF, NINF, NINF);
    float e0 = (k     < vl) ? v.x : NINF;
    float e1 = (k + 1 < vl) ? v.y : NINF;
    float e2 = (k + 2 < vl) ? v.z : NINF;
    float e3 = (k + 3 < vl) ? v.w : NINF;

    __shared__ float redm[8];
    __shared__ float reds[8];
    const int wid = tid >> 5, lid = tid & 31;

    float m = fmaxf(fmaxf(e0, e1), fmaxf(e2, e3));
    #pragma unroll
    for (int o = 16; o; o >>= 1) m = fmaxf(m, __shfl_xor_sync(~0u, m, o));
    if (lid == 0) redm[wid] = m;
    __syncthreads();
    m = redm[0];
    #pragma unroll
    for (int i = 1; i < 8; i++) m = fmaxf(m, redm[i]);

    float p0 = (k     < vl) ? __expf(e0 - m) : 0.f;
    float p1 = (k + 1 < vl) ? __expf(e1 - m) : 0.f;
    float p2 = (k + 2 < vl) ? __expf(e2 - m) : 0.f;
    float p3 = (k + 3 < vl) ? __expf(e3 - m) : 0.f;

    float s = p0 + p1 + p2 + p3;
    #pragma unroll
    for (int o = 16; o; o >>= 1) s += __shfl_xor_sync(~0u, s, o);
    if (lid == 0) reds[wid] = s;
    __syncthreads();
    s = reds[0];
    #pragma unroll
    for (int i = 1; i < 8; i++) s += reds[i];

    float inv = __frcp_rn(s);
    if (live) p[tid] = make_float4(p0 * inv, p1 * inv, p2 * inv, p3 * inv);
}

// ---------------------------------------------------------------------------
// AV partial: k split in NSLAB=4 slabs -> g_pt[s]. Tile 64q x 64v, 256 thr,
// 4q x 4v per thread, k-chunk 64, register double-buffered. 512 blocks.
// ---------------------------------------------------------------------------
__global__ void __launch_bounds__(256)
av_kernel(const float* __restrict__ values,
          const int* __restrict__ valid_lens) {
    __shared__ __align__(16) float at_s[64 * AT2];
    __shared__ __align__(16) float vs_s[64 * 64];

    const int z   = blockIdx.z;
    const int b   = z >> 2;
    const int s   = z & 3;
    const int vl  = valid_lens[b];
    const int kbeg = s * SLABK;
    if (kbeg >= vl) return;
    const int kend = (vl < kbeg + SLABK) ? vl : (kbeg + SLABK);

    const int q0  = blockIdx.y * 64;
    const int v0  = blockIdx.x * 64;
    const int tid = threadIdx.x;
    const int tx  = tid & 15;
    const int ty  = tid >> 4;

    const float* attn = g_sc + (size_t)(b * Qq + q0) * Kk + kbeg;
    const float* vals = values + ((size_t)b * Kk + kbeg) * VDd + v0;

    int lr[4];
    const int lc = tid & 15;
    #pragma unroll
    for (int i = 0; i < 4; i++) lr[i] = (i * 256 + tid) >> 4;

    float4 pa[4], pv[4];
    #pragma unroll
    for (int i = 0; i < 4; i++) {
        pa[i] = ((const float4*)(attn + (size_t)lr[i] * Kk))[lc];
        pv[i] = ((const float4*)(vals + (size_t)lr[i] * VDd))[lc];
    }

    float4 accv[4];
    #pragma unroll
    for (int i = 0; i < 4; i++) accv[i] = make_float4(0.f, 0.f, 0.f, 0.f);

    const int nchunk = (kend - kbeg + 63) >> 6;
    for (int c = 0; c < nchunk; c++) {
        #pragma unroll
        for (int i = 0; i < 4; i++) {
            ((float4*)(at_s + lr[i] * AT2))[lc] = pa[i];
            ((float4*)(vs_s + lr[i] * 64))[lc] = pv[i];
        }
        __syncthreads();

        if (c + 1 < nchunk) {
            const float* an = attn + (c + 1) * 64;
            const float* vn = vals + (size_t)(c + 1) * 64 * VDd;
            #pragma unroll
            for (int i = 0; i < 4; i++) {
                pa[i] = ((const float4*)(an + (size_t)lr[i] * Kk))[lc];
                pv[i] = ((const float4*)(vn + (size_t)lr[i] * VDd))[lc];
            }
        }

        const float* a0 = at_s + (4 * ty) * AT2;
        const float4* vrow = (const float4*)vs_s + tx;
        #pragma unroll 8
        for (int k = 0; k < 64; k++) {
            float w0 = a0[k];
            float w1 = a0[AT2 + k];
            float w2 = a0[2 * AT2 + k];
            float w3 = a0[3 * AT2 + k];
            float4 vv = vrow[k * 16];
            accv[0].x += w0 * vv.x; accv[0].y += w0 * vv.y;
            accv[0].z += w0 * vv.z; accv[0].w += w0 * vv.w;
            accv[1].x += w1 * vv.x; accv[1].y += w1 * vv.y;
            accv[1].z += w1 * vv.z; accv[1].w += w1 * vv.w;
            accv[2].x += w2 * vv.x; accv[2].y += w2 * vv.y;
            accv[2].z += w2 * vv.z; accv[2].w += w2 * vv.w;
            accv[3].x += w3 * vv.x; accv[3].y += w3 * vv.y;
            accv[3].z += w3 * vv.z; accv[3].w += w3 * vv.w;
        }
        __syncthreads();
    }

    float* pt = g_pt[s];
    #pragma unroll
    for (int i = 0; i < 4; i++) {
        float4* o = (float4*)(pt + (size_t)(b * Qq + q0 + 4 * ty + i) * VDd + v0);
        o[tx] = accv[i];
    }
}

// ---------------------------------------------------------------------------
// Reduce: out = sum over live slabs (s*SLABK < vl). 512 blocks x 256 thr.
// ---------------------------------------------------------------------------
__global__ void reduce_kernel(const int* __restrict__ valid_lens,
                              float* __restrict__ out) {
    const int e4 = blockIdx.x * 256 + threadIdx.x;    // float4 index
    const int b  = e4 >> 15;                          // (e4*4)/(Qq*VDd)
    const int vl = valid_lens[b];
    float4 r = ((const float4*)g_pt[0])[e4];
    #pragma unroll
    for (int s = 1; s < NSLAB; s++) {
        if (s * SLABK < vl) {
            float4 r1 = ((const float4*)g_pt[s])[e4];
            r.x += r1.x; r.y += r1.y; r.z += r1.z; r.w += r1.w;
        }
    }
    ((float4*)out)[e4] = r;
}

// ---------------------------------------------------------------------------
extern "C" void kernel_launch(void* const* d_in, const int* in_sizes, int n_in,
                              void* d_out, int out_size) {
    const float* queries    = (const float*)d_in[0];
    const float* keys       = (const float*)d_in[1];
    const float* values     = (const float*)d_in[2];
    const int*   valid_lens = (const int*)  d_in[3];
    const float* W_q        = (const float*)d_in[4];
    const float* W_k        = (const float*)d_in[5];
    const float* w_v        = (const float*)d_in[6];
    float* out = (float*)d_out;

    proj_kernel<<<(Bb * Qq) / 16 + (Bb * Kk) / 16, 256>>>(queries, W_q, keys, W_k);

    const int sc_smem = (3 * 128 * 64 + 128) * (int)sizeof(float);   // ~96.5 KB
    cudaFuncSetAttribute(scores_kernel, cudaFuncAttributeMaxDynamicSharedMemorySize,
                         sc_smem);
    scores_kernel<<<dim3(Kk / 64, Qq / 64, Bb), 256, sc_smem>>>(w_v, valid_lens);

    softmax_kernel<<<Bb * Qq, 256>>>(valid_lens);

    av_kernel<<<dim3(VDd / 64, Qq / 64, NSLAB * Bb), 256>>>(values, valid_lens);

    reduce_kernel<<<(Bb * Qq * VDd) / 1024, 256>>>(valid_lens, out);
}

// round 13
// speedup vs baseline: 1.0980x; 1.0980x over previous
#include <cuda_runtime.h>
#include <cstdint>

#define Bb 4
#define Qq 512
#define Kk 1024
#define VDd 256
#define Hh 128

#define AT2 68          // av attn smem stride (floats)
#define NSLAB 4
#define SLABK 256

// Scratch (no allocations allowed).
__device__ __align__(16) float g_qp[Bb * Qq * Hh];             // 1 MB
__device__ __align__(16) float g_kp[Bb * Kk * Hh];             // 2 MB
__device__ __align__(16) float g_sc[Bb * Qq * Kk];             // 8 MB
__device__ __align__(16) float g_pt[NSLAB][Bb * Qq * VDd];     // 8 MB partials

__device__ __forceinline__ float tanh_fast(float x) {
    float y;
    asm("tanh.approx.f32 %0, %1;" : "=f"(y) : "f"(x));
    return y;
}

// ---------------------------------------------------------------------------
// Combined projection: g_qp = queries@W_q, g_kp = keys@W_k. 384 blocks.
// ---------------------------------------------------------------------------
__global__ void __launch_bounds__(256)
proj_kernel(const float* __restrict__ queries,
            const float* __restrict__ W_q,
            const float* __restrict__ keys,
            const float* __restrict__ W_k) {
    __shared__ __align__(16) float a_s[16][260];
    __shared__ __align__(16) float w_t[128][36];

    const int bx = blockIdx.x;
    const float* A; const float* W; float* C; int row0;
    if (bx < (Bb * Qq) / 16) { A = queries; W = W_q; C = g_qp; row0 = bx * 16; }
    else { A = keys; W = W_k; C = g_kp; row0 = (bx - (Bb * Qq) / 16) * 16; }

    const int tid = threadIdx.x;

    const float4* A4 = (const float4*)(A + (size_t)row0 * 256);
    #pragma unroll
    for (int i = 0; i < 4; i++) {
        int e = i * 256 + tid;
        ((float4*)&a_s[e >> 6][0])[e & 63] = A4[e];
    }

    const int col = tid & 127;
    const int rg  = tid >> 7;
    float acc[8];
    #pragma unroll
    for (int i = 0; i < 8; i++) acc[i] = 0.f;

    for (int dc = 0; dc < 256; dc += 32) {
        __syncthreads();
        #pragma unroll
        for (int i = 0; i < 16; i++) {
            int idx = i * 256 + tid;
            int r = idx >> 7, c = idx & 127;
            w_t[c][r] = W[(size_t)(dc + r) * 128 + c];
        }
        __syncthreads();
        const float4* wv4 = (const float4*)&w_t[col][0];
        #pragma unroll
        for (int d4 = 0; d4 < 8; d4++) {
            float4 wv = wv4[d4];
            #pragma unroll
            for (int i = 0; i < 8; i++) {
                float4 av = ((const float4*)&a_s[rg * 8 + i][dc])[d4];
                acc[i] += av.x * wv.x + av.y * wv.y + av.z * wv.z + av.w * wv.w;
            }
        }
    }
    __syncthreads();
    #pragma unroll
    for (int i = 0; i < 8; i++)
        C[(size_t)(row0 + rg * 8 + i) * 128 + col] = acc[i];
}

// ---------------------------------------------------------------------------
// Scores: 64q x 64k tile, 4x4 micro-tile, fp32 tanh. Smem tiles transposed
// [h][row] -> inner loop per h: 1 bcast LDS + 2 LDS.128 + 16(FADD,TANH,FFMA).
// MUFU-saturated. Masked tiles (k0 >= valid_len) exit immediately.
// ---------------------------------------------------------------------------
__global__ void __launch_bounds__(256)
scores_kernel(const float* __restrict__ w_v,
              const int* __restrict__ valid_lens) {
    const int b  = blockIdx.z;
    const int k0 = blockIdx.x * 64;
    if (k0 >= valid_lens[b]) return;
    const int q0 = blockIdx.y * 64;

    extern __shared__ float sm[];
    float* qt = sm;                  // [h][qrow] 128*64 = 32 KB
    float* kt = qt + 128 * 64;       // [h][krow] 32 KB
    float* ws = kt + 128 * 64;       // 128

    const int tid = threadIdx.x;
    if (tid < 128) ws[tid] = w_v[tid];

    const float4* qp4 = (const float4*)(g_qp + (size_t)(b * Qq + q0) * Hh);
    const float4* kp4 = (const float4*)(g_kp + (size_t)(b * Kk + k0) * Hh);

    // Load + transpose. Task t: row = t&63, c4 = t>>6 (f4 h-col 0..31).
    #pragma unroll
    for (int i = 0; i < 8; i++) {
        int t   = i * 256 + tid;
        int row = t & 63, c4 = t >> 6;
        float4 qv = qp4[row * 32 + c4];
        float4 kv = kp4[row * 32 + c4];
        int h = 4 * c4;
        qt[(h + 0) * 64 + row] = qv.x;
        qt[(h + 1) * 64 + row] = qv.y;
        qt[(h + 2) * 64 + row] = qv.z;
        qt[(h + 3) * 64 + row] = qv.w;
        kt[(h + 0) * 64 + row] = kv.x;
        kt[(h + 1) * 64 + row] = kv.y;
        kt[(h + 2) * 64 + row] = kv.z;
        kt[(h + 3) * 64 + row] = kv.w;
    }
    __syncthreads();

    const int tx = tid & 15;   // k rows 4tx..4tx+3
    const int ty = tid >> 4;   // q rows 4ty..4ty+3

    float acc[4][4];
    #pragma unroll
    for (int i = 0; i < 4; i++)
        #pragma unroll
        for (int j = 0; j < 4; j++) acc[i][j] = 0.f;

    #pragma unroll 4
    for (int h = 0; h < 128; h++) {
        float w = ws[h];
        float4 qv = *(const float4*)&qt[h * 64 + 4 * ty];
        float4 kv = *(const float4*)&kt[h * 64 + 4 * tx];
        float qa[4] = {qv.x, qv.y, qv.z, qv.w};
        float ka[4] = {kv.x, kv.y, kv.z, kv.w};
        #pragma unroll
        for (int i = 0; i < 4; i++)
            #pragma unroll
            for (int j = 0; j < 4; j++)
                acc[i][j] = fmaf(w, tanh_fast(qa[i] + ka[j]), acc[i][j]);
    }

    #pragma unroll
    for (int i = 0; i < 4; i++) {
        float4 r = make_float4(acc[i][0], acc[i][1], acc[i][2], acc[i][3]);
        *(float4*)&g_sc[(size_t)(b * Qq + q0 + 4 * ty + i) * Kk + k0 + 4 * tx] = r;
    }
}

// ---------------------------------------------------------------------------
// Softmax over k < vl; zeros written up to roundup(vl,64) (AV reads that far).
// ---------------------------------------------------------------------------
__global__ void softmax_kernel(const int* __restrict__ valid_lens) {
    const int row = blockIdx.x;
    const int b   = row >> 9;
    const int vl  = valid_lens[b];
    const int vl64 = (vl + 63) & ~63;
    const int tid = threadIdx.x;
    const float NINF = __int_as_float(0xff800000);

    float4* p = (float4*)&g_sc[(size_t)row * Kk];
    const int k = 4 * tid;
    const bool live = (k < vl64);
    float4 v = live ? p[tid] : make_float4(NINF, NINF, NINF, NINF);
    float e0 = (k     < vl) ? v.x : NINF;
    float e1 = (k + 1 < vl) ? v.y : NINF;
    float e2 = (k + 2 < vl) ? v.z : NINF;
    float e3 = (k + 3 < vl) ? v.w : NINF;

    __shared__ float redm[8];
    __shared__ float reds[8];
    const int wid = tid >> 5, lid = tid & 31;

    float m = fmaxf(fmaxf(e0, e1), fmaxf(e2, e3));
    #pragma unroll
    for (int o = 16; o; o >>= 1) m = fmaxf(m, __shfl_xor_sync(~0u, m, o));
    if (lid == 0) redm[wid] = m;
    __syncthreads();
    m = redm[0];
    #pragma unroll
    for (int i = 1; i < 8; i++) m = fmaxf(m, redm[i]);

    float p0 = (k     < vl) ? __expf(e0 - m) : 0.f;
    float p1 = (k + 1 < vl) ? __expf(e1 - m) : 0.f;
    float p2 = (k + 2 < vl) ? __expf(e2 - m) : 0.f;
    float p3 = (k + 3 < vl) ? __expf(e3 - m) : 0.f;

    float s = p0 + p1 + p2 + p3;
    #pragma unroll
    for (int o = 16; o; o >>= 1) s += __shfl_xor_sync(~0u, s, o);
    if (lid == 0) reds[wid] = s;
    __syncthreads();
    s = reds[0];
    #pragma unroll
    for (int i = 1; i < 8; i++) s += reds[i];

    float inv = __frcp_rn(s);
    if (live) p[tid] = make_float4(p0 * inv, p1 * inv, p2 * inv, p3 * inv);
}

// ---------------------------------------------------------------------------
// AV partial: k split in NSLAB=4 slabs -> g_pt[s]. Tile 64q x 64v, 256 thr,
// 4q x 4v per thread. k unrolled by 4: attn read as float4 row-segments
// (broadcast) -> 8 LDS.128 + 64 FFMA per 4k: fma-pipe-bound. 512 blocks.
// ---------------------------------------------------------------------------
__global__ void __launch_bounds__(256)
av_kernel(const float* __restrict__ values,
          const int* __restrict__ valid_lens) {
    __shared__ __align__(16) float at_s[64 * AT2];
    __shared__ __align__(16) float vs_s[64 * 64];

    const int z   = blockIdx.z;
    const int b   = z >> 2;
    const int s   = z & 3;
    const int vl  = valid_lens[b];
    const int kbeg = s * SLABK;
    if (kbeg >= vl) return;
    const int kend = (vl < kbeg + SLABK) ? vl : (kbeg + SLABK);

    const int q0  = blockIdx.y * 64;
    const int v0  = blockIdx.x * 64;
    const int tid = threadIdx.x;
    const int tx  = tid & 15;
    const int ty  = tid >> 4;

    const float* attn = g_sc + (size_t)(b * Qq + q0) * Kk + kbeg;
    const float* vals = values + ((size_t)b * Kk + kbeg) * VDd + v0;

    int lr[4];
    const int lc = tid & 15;
    #pragma unroll
    for (int i = 0; i < 4; i++) lr[i] = (i * 256 + tid) >> 4;

    float4 pa[4], pv[4];
    #pragma unroll
    for (int i = 0; i < 4; i++) {
        pa[i] = ((const float4*)(attn + (size_t)lr[i] * Kk))[lc];
        pv[i] = ((const float4*)(vals + (size_t)lr[i] * VDd))[lc];
    }

    float4 accv[4];
    #pragma unroll
    for (int i = 0; i < 4; i++) accv[i] = make_float4(0.f, 0.f, 0.f, 0.f);

    const int nchunk = (kend - kbeg + 63) >> 6;
    for (int c = 0; c < nchunk; c++) {
        #pragma unroll
        for (int i = 0; i < 4; i++) {
            ((float4*)(at_s + lr[i] * AT2))[lc] = pa[i];
            ((float4*)(vs_s + lr[i] * 64))[lc] = pv[i];
        }
        __syncthreads();

        if (c + 1 < nchunk) {
            const float* an = attn + (c + 1) * 64;
            const float* vn = vals + (size_t)(c + 1) * 64 * VDd;
            #pragma unroll
            for (int i = 0; i < 4; i++) {
                pa[i] = ((const float4*)(an + (size_t)lr[i] * Kk))[lc];
                pv[i] = ((const float4*)(vn + (size_t)lr[i] * VDd))[lc];
            }
        }

        const float* a0 = at_s + (4 * ty) * AT2;
        const float4* vrow = (const float4*)vs_s + tx;
        #pragma unroll 4
        for (int k4 = 0; k4 < 16; k4++) {
            float4 a0v = *(const float4*)&a0[4 * k4];
            float4 a1v = *(const float4*)&a0[AT2 + 4 * k4];
            float4 a2v = *(const float4*)&a0[2 * AT2 + 4 * k4];
            float4 a3v = *(const float4*)&a0[3 * AT2 + 4 * k4];
            float4 vv;
            vv = vrow[(4 * k4 + 0) * 16];
            accv[0].x += a0v.x * vv.x; accv[0].y += a0v.x * vv.y;
            accv[0].z += a0v.x * vv.z; accv[0].w += a0v.x * vv.w;
            accv[1].x += a1v.x * vv.x; accv[1].y += a1v.x * vv.y;
            accv[1].z += a1v.x * vv.z; accv[1].w += a1v.x * vv.w;
            accv[2].x += a2v.x * vv.x; accv[2].y += a2v.x * vv.y;
            accv[2].z += a2v.x * vv.z; accv[2].w += a2v.x * vv.w;
            accv[3].x += a3v.x * vv.x; accv[3].y += a3v.x * vv.y;
            accv[3].z += a3v.x * vv.z; accv[3].w += a3v.x * vv.w;
            vv = vrow[(4 * k4 + 1) * 16];
            accv[0].x += a0v.y * vv.x; accv[0].y += a0v.y * vv.y;
            accv[0].z += a0v.y * vv.z; accv[0].w += a0v.y * vv.w;
            accv[1].x += a1v.y * vv.x; accv[1].y += a1v.y * vv.y;
            accv[1].z += a1v.y * vv.z; accv[1].w += a1v.y * vv.w;
            accv[2].x += a2v.y * vv.x; accv[2].y += a2v.y * vv.y;
            accv[2].z += a2v.y * vv.z; accv[2].w += a2v.y * vv.w;
            accv[3].x += a3v.y * vv.x; accv[3].y += a3v.y * vv.y;
            accv[3].z += a3v.y * vv.z; accv[3].w += a3v.y * vv.w;
            vv = vrow[(4 * k4 + 2) * 16];
            accv[0].x += a0v.z * vv.x; accv[0].y += a0v.z * vv.y;
            accv[0].z += a0v.z * vv.z; accv[0].w += a0v.z * vv.w;
            accv[1].x += a1v.z * vv.x; accv[1].y += a1v.z * vv.y;
            accv[1].z += a1v.z * vv.z; accv[1].w += a1v.z * vv.w;
            accv[2].x += a2v.z * vv.x; accv[2].y += a2v.z * vv.y;
            accv[2].z += a2v.z * vv.z; accv[2].w += a2v.z * vv.w;
            accv[3].x += a3v.z * vv.x; accv[3].y += a3v.z * vv.y;
            accv[3].z += a3v.z * vv.z; accv[3].w += a3v.z * vv.w;
            vv = vrow[(4 * k4 + 3) * 16];
            accv[0].x += a0v.w * vv.x; accv[0].y += a0v.w * vv.y;
            accv[0].z += a0v.w * vv.z; accv[0].w += a0v.w * vv.w;
            accv[1].x += a1v.w * vv.x; accv[1].y += a1v.w * vv.y;
            accv[1].z += a1v.w * vv.z; accv[1].w += a1v.w * vv.w;
            accv[2].x += a2v.w * vv.x; accv[2].y += a2v.w * vv.y;
            accv[2].z += a2v.w * vv.z; accv[2].w += a2v.w * vv.w;
            accv[3].x += a3v.w * vv.x; accv[3].y += a3v.w * vv.y;
            accv[3].z += a3v.w * vv.z; accv[3].w += a3v.w * vv.w;
        }
        __syncthreads();
    }

    float* pt = g_pt[s];
    #pragma unroll
    for (int i = 0; i < 4; i++) {
        float4* o = (float4*)(pt + (size_t)(b * Qq + q0 + 4 * ty + i) * VDd + v0);
        o[tx] = accv[i];
    }
}

// ---------------------------------------------------------------------------
// Reduce: out = sum over live slabs (s*SLABK < vl). 512 blocks x 256 thr.
// ---------------------------------------------------------------------------
__global__ void reduce_kernel(const int* __restrict__ valid_lens,
                              float* __restrict__ out) {
    const int e4 = blockIdx.x * 256 + threadIdx.x;
    const int b  = e4 >> 15;
    const int vl = valid_lens[b];
    float4 r = ((const float4*)g_pt[0])[e4];
    #pragma unroll
    for (int s = 1; s < NSLAB; s++) {
        if (s * SLABK < vl) {
            float4 r1 = ((const float4*)g_pt[s])[e4];
            r.x += r1.x; r.y += r1.y; r.z += r1.z; r.w += r1.w;
        }
    }
    ((float4*)out)[e4] = r;
}

// ---------------------------------------------------------------------------
extern "C" void kernel_launch(void* const* d_in, const int* in_sizes, int n_in,
                              void* d_out, int out_size) {
    const float* queries    = (const float*)d_in[0];
    const float* keys       = (const float*)d_in[1];
    const float* values     = (const float*)d_in[2];
    const int*   valid_lens = (const int*)  d_in[3];
    const float* W_q        = (const float*)d_in[4];
    const float* W_k        = (const float*)d_in[5];
    const float* w_v        = (const float*)d_in[6];
    float* out = (float*)d_out;

    proj_kernel<<<(Bb * Qq) / 16 + (Bb * Kk) / 16, 256>>>(queries, W_q, keys, W_k);

    const int sc_smem = (2 * 128 * 64 + 128) * (int)sizeof(float);   // ~64.5 KB
    cudaFuncSetAttribute(scores_kernel, cudaFuncAttributeMaxDynamicSharedMemorySize,
                         sc_smem);
    scores_kernel<<<dim3(Kk / 64, Qq / 64, Bb), 256, sc_smem>>>(w_v, valid_lens);

    softmax_kernel<<<Bb * Qq, 256>>>(valid_lens);

    av_kernel<<<dim3(VDd / 64, Qq / 64, NSLAB * Bb), 256>>>(values, valid_lens);

    reduce_kernel<<<(Bb * Qq * VDd) / 1024, 256>>>(valid_lens, out);
}